// round 8
// baseline (speedup 1.0000x reference)
#include <cuda_runtime.h>

#define N_NODES   100000
#define N_EDGES   600000
#define D_FEAT    128
#define N_CLASSES 40
#define NB_SCAN   391        // ceil(N_NODES / 256)
#define CHUNK     8          // gathers kept in flight per agg iteration

// Scratch (allocation-free rule: __device__ globals).
__device__ float g_bufA[(size_t)N_NODES * D_FEAT];
__device__ float g_bufB[(size_t)N_NODES * D_FEAT];
__device__ int   g_deg[N_NODES];
__device__ float g_dinv[N_NODES];
__device__ int   g_rowstart[N_NODES];
__device__ int   g_cursor[N_NODES];
__device__ int   g_csr[N_EDGES];        // src ids grouped by dst
__device__ int   g_blocksum[NB_SCAN];
__device__ int   g_blockoff[NB_SCAN];
__device__ unsigned g_fmt;              // 0 -> edge_index int64, else int32

// ---- init: zero deg, reset dtype probe ------------------------------------
__global__ void k_init() {
    int i = blockIdx.x * blockDim.x + threadIdx.x;
    if (i == 0) g_fmt = 0u;
    if (i < N_NODES) g_deg[i] = 0;
}

// dtype probe: OR all odd int32 words. int64 node ids (<1e5) have zero high
// halves -> OR==0; int32 layout puts random ids there -> OR!=0.
__global__ void k_probe(const int* __restrict__ e32) {
    int i = blockIdx.x * blockDim.x + threadIdx.x;
    unsigned v = 0;
    if (i < N_EDGES) v = (unsigned)e32[2 * i + 1];
    #pragma unroll
    for (int off = 16; off; off >>= 1)
        v |= __shfl_xor_sync(0xffffffffu, v, off);
    if ((threadIdx.x & 31) == 0 && v) atomicOr(&g_fmt, v);
}

__device__ __forceinline__ void decode_edge(const int* __restrict__ e32,
                                            int e, int& s, int& d) {
    if (g_fmt) { s = e32[e];     d = e32[N_EDGES + e]; }
    else       { s = e32[2 * e]; d = e32[2 * (N_EDGES + e)]; }
    if ((unsigned)s >= N_NODES) s = 0;   // defensive: soft-fail, no trap
    if ((unsigned)d >= N_NODES) d = 0;
}

// count in-degree (decode on the fly)
__global__ void k_count(const int* __restrict__ e32) {
    int e = blockIdx.x * blockDim.x + threadIdx.x;
    if (e >= N_EDGES) return;
    int s, d;
    decode_edge(e32, e, s, d);
    atomicAdd(&g_deg[d], 1);
}

// ---- block scan of deg (+ fused dinv computation) -------------------------
__global__ void k_block_scan() {
    int tid = threadIdx.x, lane = tid & 31, warp = tid >> 5;
    int i = blockIdx.x * 256 + tid;
    int v = (i < N_NODES) ? g_deg[i] : 0;
    if (i < N_NODES) g_dinv[i] = rsqrtf((float)v + 1.0f);   // fused
    int x = v;
    #pragma unroll
    for (int off = 1; off < 32; off <<= 1) {
        int y = __shfl_up_sync(0xffffffffu, x, off);
        if (lane >= off) x += y;
    }
    __shared__ int wsum[8];
    if (lane == 31) wsum[warp] = x;
    __syncthreads();
    if (tid < 8) {
        int wv = wsum[tid];
        #pragma unroll
        for (int off = 1; off < 8; off <<= 1) {
            int y = __shfl_up_sync(0xffu, wv, off);
            if (tid >= off) wv += y;
        }
        wsum[tid] = wv;                 // inclusive warp sums
    }
    __syncthreads();
    int base = (warp > 0) ? wsum[warp - 1] : 0;
    int incl = x + base;
    if (i < N_NODES) g_rowstart[i] = incl - v;   // block-local exclusive
    if (tid == 255) g_blocksum[blockIdx.x] = incl;
}

__global__ void k_scan_sums() {       // 1 block, 512 threads; NB_SCAN=391<512
    int tid = threadIdx.x, lane = tid & 31, warp = tid >> 5;
    int v = (tid < NB_SCAN) ? g_blocksum[tid] : 0;
    int x = v;
    #pragma unroll
    for (int off = 1; off < 32; off <<= 1) {
        int y = __shfl_up_sync(0xffffffffu, x, off);
        if (lane >= off) x += y;
    }
    __shared__ int wsum[16];
    if (lane == 31) wsum[warp] = x;
    __syncthreads();
    if (tid < 16) {
        int wv = wsum[tid];
        #pragma unroll
        for (int off = 1; off < 16; off <<= 1) {
            int y = __shfl_up_sync(0xffffu, wv, off);
            if (tid >= off) wv += y;
        }
        wsum[tid] = wv;
    }
    __syncthreads();
    int base = (warp > 0) ? wsum[warp - 1] : 0;
    if (tid < NB_SCAN) g_blockoff[tid] = x + base - v;   // exclusive
}

__global__ void k_finalize() {
    int i = blockIdx.x * blockDim.x + threadIdx.x;
    if (i >= N_NODES) return;
    int rs = g_rowstart[i] + g_blockoff[i >> 8];
    g_rowstart[i] = rs;
    g_cursor[i]   = rs;
}

// ---- bin edges into CSR ---------------------------------------------------
__global__ void k_bin(const int* __restrict__ e32) {
    int e = blockIdx.x * blockDim.x + threadIdx.x;
    if (e >= N_EDGES) return;
    int s, d;
    decode_edge(e32, e, s, d);
    int pos = atomicAdd(&g_cursor[d], 1);
    g_csr[pos] = s;
}

// ---- round 1: bufB = dinv^2 * ( dinv[w]*x[w] + sum dinv[s]*x[s] ) ---------
// (produces u2 directly from raw x; scale_init pass eliminated)
__global__ void k_agg1(const float4* __restrict__ x) {
    int w    = (blockIdx.x * blockDim.x + threadIdx.x) >> 5;
    int lane = threadIdx.x & 31;
    if (w >= N_NODES) return;
    int r0 = g_rowstart[w];
    int r1 = r0 + g_deg[w];
    float dv = g_dinv[w];

    float4 acc = x[w * 32 + lane];
    acc.x *= dv; acc.y *= dv; acc.z *= dv; acc.w *= dv;   // self term

    int e = r0;
    while (e < r1) {
        int n = r1 - e; if (n > CHUNK) n = CHUNK;
        int   idx[CHUNK];
        float wt[CHUNK];
        #pragma unroll
        for (int j = 0; j < CHUNK; j++)           // independent broadcast loads
            idx[j] = (j < n) ? g_csr[e + j] : 0;
        #pragma unroll
        for (int j = 0; j < CHUNK; j++)
            wt[j] = (j < n) ? g_dinv[idx[j]] : 0.0f;
        float4 v[CHUNK];
        #pragma unroll
        for (int j = 0; j < CHUNK; j++)           // all gathers in flight
            if (j < n) v[j] = x[idx[j] * 32 + lane];
        #pragma unroll
        for (int j = 0; j < CHUNK; j++)
            if (j < n) {
                acc.x = fmaf(wt[j], v[j].x, acc.x);
                acc.y = fmaf(wt[j], v[j].y, acc.y);
                acc.z = fmaf(wt[j], v[j].z, acc.z);
                acc.w = fmaf(wt[j], v[j].w, acc.w);
            }
        e += n;
    }
    float sc = dv * dv;
    acc.x *= sc; acc.y *= sc; acc.z *= sc; acc.w *= sc;
    ((float4*)g_bufB)[w * 32 + lane] = acc;
}

// ---- round 2: bufA = dinv * ( u2[w] + sum u2[s] ) -------------------------
__global__ void k_agg2() {
    const float4* __restrict__ src = (const float4*)g_bufB;
    int w    = (blockIdx.x * blockDim.x + threadIdx.x) >> 5;
    int lane = threadIdx.x & 31;
    if (w >= N_NODES) return;
    int r0 = g_rowstart[w];
    int r1 = r0 + g_deg[w];

    float4 acc = src[w * 32 + lane];              // self term

    int e = r0;
    while (e < r1) {
        int n = r1 - e; if (n > CHUNK) n = CHUNK;
        int idx[CHUNK];
        #pragma unroll
        for (int j = 0; j < CHUNK; j++)
            idx[j] = (j < n) ? g_csr[e + j] : 0;
        float4 v[CHUNK];
        #pragma unroll
        for (int j = 0; j < CHUNK; j++)
            if (j < n) v[j] = src[idx[j] * 32 + lane];
        #pragma unroll
        for (int j = 0; j < CHUNK; j++)
            if (j < n) {
                acc.x += v[j].x; acc.y += v[j].y;
                acc.z += v[j].z; acc.w += v[j].w;
            }
        e += n;
    }
    float dv = g_dinv[w];
    acc.x *= dv; acc.y *= dv; acc.z *= dv; acc.w *= dv;
    ((float4*)g_bufA)[w * 32 + lane] = acc;
}

// ---- classifier: logits = bufA @ W^T + b ; log_softmax --------------------
__global__ void k_classify(const float* __restrict__ W,
                           const float* __restrict__ b,
                           float* __restrict__ out) {
    __shared__ float2 Wp[D_FEAT * 32];
    __shared__ float  bsh[64];
    __shared__ float  xsh[8][D_FEAT];

    for (int idx = threadIdx.x; idx < D_FEAT * 32; idx += blockDim.x) {
        int k = idx >> 5, c = idx & 31;
        float w0 = W[c * D_FEAT + k];
        float w1 = (c + 32 < N_CLASSES) ? W[(c + 32) * D_FEAT + k] : 0.0f;
        Wp[idx] = make_float2(w0, w1);
    }
    if (threadIdx.x < 64)
        bsh[threadIdx.x] = (threadIdx.x < N_CLASSES) ? b[threadIdx.x] : 0.0f;
    __syncthreads();

    int lane   = threadIdx.x & 31;
    int wlocal = threadIdx.x >> 5;
    int gwarp  = blockIdx.x * (blockDim.x >> 5) + wlocal;
    int nwarps = gridDim.x * (blockDim.x >> 5);

    for (int node = gwarp; node < N_NODES; node += nwarps) {
        float4 xv = ((const float4*)g_bufA)[node * 32 + lane];
        ((float4*)xsh[wlocal])[lane] = xv;
        __syncwarp();

        float acc0 = bsh[lane];
        float acc1 = bsh[lane + 32];
        #pragma unroll 8
        for (int k = 0; k < D_FEAT; k++) {
            float xk = xsh[wlocal][k];
            float2 wp = Wp[(k << 5) | lane];
            acc0 = fmaf(xk, wp.x, acc0);
            acc1 = fmaf(xk, wp.y, acc1);
        }

        float v1 = (lane < 8) ? acc1 : -1e30f;
        float m = fmaxf(acc0, v1);
        #pragma unroll
        for (int off = 16; off; off >>= 1)
            m = fmaxf(m, __shfl_xor_sync(0xffffffffu, m, off));
        float s = expf(acc0 - m) + ((lane < 8) ? expf(acc1 - m) : 0.0f);
        #pragma unroll
        for (int off = 16; off; off >>= 1)
            s += __shfl_xor_sync(0xffffffffu, s, off);
        float ls = m + logf(s);

        out[node * N_CLASSES + lane] = acc0 - ls;
        if (lane < 8)
            out[node * N_CLASSES + 32 + lane] = acc1 - ls;
        __syncwarp();
    }
}

extern "C" void kernel_launch(void* const* d_in, const int* in_sizes, int n_in,
                              void* d_out, int out_size) {
    const float* x  = (const float*)d_in[0];
    const int*   ei = (const int*)d_in[1];   // dtype resolved on device (g_fmt)
    const float* W  = (const float*)d_in[2];
    const float* b  = (const float*)d_in[3];
    float* out = (float*)d_out;

    const int T = 256;
    const int nodeBlocks = (N_NODES + T - 1) / T;                 // 391
    const int edgeBlocks = (N_EDGES + T - 1) / T;                 // 2344
    const int aggBlocks  = (N_NODES * 32 + T - 1) / T;            // 12500

    k_init       <<<nodeBlocks, T>>>();
    k_probe      <<<edgeBlocks, T>>>(ei);
    k_count      <<<edgeBlocks, T>>>(ei);
    k_block_scan <<<NB_SCAN,    T>>>();
    k_scan_sums  <<<1,        512>>>();
    k_finalize   <<<nodeBlocks, T>>>();
    k_bin        <<<edgeBlocks, T>>>(ei);
    k_agg1       <<<aggBlocks,  T>>>((const float4*)x);
    k_agg2       <<<aggBlocks,  T>>>();
    k_classify   <<<1184,       T>>>(W, b, out);
}